// round 2
// baseline (speedup 1.0000x reference)
#include <cuda_runtime.h>
#include <math.h>

#define BB   128   // batch
#define TT   512   // timesteps
#define NN   512   // hidden
#define NCTA 128   // persistent CTAs
#define JT   4     // output columns per CTA (NN / NCTA)
#define NTHR 256

// -------- persistent device state (no allocations allowed) --------
__device__ float g_c[2][NN * BB];        // state c, [n][b] transposed, double buffered
__device__ float g_h[2][NN * BB];        // state h, [n][b] transposed, double buffered
__device__ float g_fpart[NCTA * BB];     // per-CTA partial f sums
__device__ unsigned int g_bar;           // monotonic barrier counter

// -------- init: reset barrier, transpose initial state --------
__global__ void hippo_init(const float* __restrict__ h0, const float* __restrict__ c0) {
    int idx = blockIdx.x * blockDim.x + threadIdx.x;
    if (idx == 0) g_bar = 0u;
    int total = NN * BB;
    for (int i = idx; i < total; i += gridDim.x * blockDim.x) {
        int n = i / BB;
        int b = i % BB;
        g_c[0][i] = c0[b * NN + n];
        g_h[0][i] = h0[b * NN + n];
    }
}

// -------- split grid barrier (arrive / wait), monotonic counter --------
__device__ __forceinline__ void bar_arrive() {
    __syncthreads();
    if (threadIdx.x == 0) {
        __threadfence();
        atomicAdd(&g_bar, 1u);
    }
}
__device__ __forceinline__ void bar_wait(unsigned int target) {
    if (threadIdx.x == 0) {
        while (atomicAdd(&g_bar, 0u) < target) { __nanosleep(64); }
        __threadfence();
    }
    __syncthreads();
}

__global__ __launch_bounds__(NTHR, 1) void hippo_persistent(
    const float* __restrict__ x,        // (B,T,1)
    const float* __restrict__ Wi,       // (N, N+1)
    const float* __restrict__ bi,       // (N)
    const float* __restrict__ Wh,       // (N, N+1)
    const float* __restrict__ bh,       // (N)
    const float* __restrict__ Wf,       // (1, N+1)
    const float* __restrict__ bfv,      // (1)
    const float* __restrict__ A_stack,  // (T,N,N)
    const float* __restrict__ B_stack,  // (T,N)
    float* __restrict__ out)            // hs (B,T,N) then c_f (B,N)
{
    __shared__ float Wi_s[JT][NN];
    __shared__ float Wh_s[JT][NN];
    __shared__ float fc_s[JT][BB];
    __shared__ float f_s[BB];
    __shared__ float wx_s[JT];   // Wi[j,0] + Wh[j,0]
    __shared__ float bb_s[JT];   // bi[j] + bh[j]
    __shared__ float wf_s[JT];   // Wf[0, j+1]

    const int cta = blockIdx.x;
    const int j0  = cta * JT;
    const int tid = threadIdx.x;
    const int jl  = tid >> 6;        // 0..3   (uniform per warp)
    const int g   = tid & 63;
    const int b0  = g * 2;           // this thread handles batches b0, b0+1
    const int jg  = j0 + jl;

    // preload weight slices into SMEM (held for whole run)
    for (int i = tid; i < JT * NN; i += NTHR) {
        int r = i / NN, k = i % NN;
        Wi_s[r][k] = Wi[(j0 + r) * (NN + 1) + 1 + k];
        Wh_s[r][k] = Wh[(j0 + r) * (NN + 1) + 1 + k];
    }
    if (tid < JT) {
        wx_s[tid] = Wi[(j0 + tid) * (NN + 1)] + Wh[(j0 + tid) * (NN + 1)];
        bb_s[tid] = bi[j0 + tid] + bh[j0 + tid];
        wf_s[tid] = Wf[1 + j0 + tid];
    }
    __syncthreads();

    const float wf0 = Wf[0];
    const float bf0 = bfv[0];

    float* out_hs = out;
    float* out_cf = out + (size_t)BB * TT * NN;

    for (int t = 0; t < TT; ++t) {
        const int cur = t & 1, nxt = cur ^ 1;
        const float* c_cur = g_c[cur];
        const float* h_cur = g_h[cur];

        // ================= phase 1: gates -> h_new, f partials =================
        float a0 = 0.f, a1 = 0.f;
        {
            const float* wi = Wi_s[jl];
            const float* wh = Wh_s[jl];
            #pragma unroll 4
            for (int k = 0; k < NN; k += 4) {
                float4 wi4 = *(const float4*)(wi + k);
                float4 wh4 = *(const float4*)(wh + k);
                float2 c2, h2;
                c2 = __ldcg((const float2*)(c_cur + (k + 0) * BB + b0));
                h2 = __ldcg((const float2*)(h_cur + (k + 0) * BB + b0));
                a0 += wi4.x * c2.x + wh4.x * h2.x;  a1 += wi4.x * c2.y + wh4.x * h2.y;
                c2 = __ldcg((const float2*)(c_cur + (k + 1) * BB + b0));
                h2 = __ldcg((const float2*)(h_cur + (k + 1) * BB + b0));
                a0 += wi4.y * c2.x + wh4.y * h2.x;  a1 += wi4.y * c2.y + wh4.y * h2.y;
                c2 = __ldcg((const float2*)(c_cur + (k + 2) * BB + b0));
                h2 = __ldcg((const float2*)(h_cur + (k + 2) * BB + b0));
                a0 += wi4.z * c2.x + wh4.z * h2.x;  a1 += wi4.z * c2.y + wh4.z * h2.y;
                c2 = __ldcg((const float2*)(c_cur + (k + 3) * BB + b0));
                h2 = __ldcg((const float2*)(h_cur + (k + 3) * BB + b0));
                a0 += wi4.w * c2.x + wh4.w * h2.x;  a1 += wi4.w * c2.y + wh4.w * h2.y;
            }
        }
        {
            float xb0 = x[(b0 + 0) * TT + t];
            float xb1 = x[(b0 + 1) * TT + t];
            float gate0 = a0 + bb_s[jl] + wx_s[jl] * xb0;
            float gate1 = a1 + bb_s[jl] + wx_s[jl] * xb1;
            float o0 = 1.f / (1.f + expf(-gate0));
            float o1 = 1.f / (1.f + expf(-gate1));
            float cj0 = __ldcg(c_cur + jg * BB + b0);
            float cj1 = __ldcg(c_cur + jg * BB + b0 + 1);
            float hn0 = o0 * tanhf(cj0);
            float hn1 = o1 * tanhf(cj1);
            g_h[nxt][jg * BB + b0]     = hn0;
            g_h[nxt][jg * BB + b0 + 1] = hn1;
            out_hs[(size_t)(b0 + 0) * TT * NN + (size_t)t * NN + jg] = hn0;
            out_hs[(size_t)(b0 + 1) * TT * NN + (size_t)t * NN + jg] = hn1;
            fc_s[jl][b0]     = wf_s[jl] * hn0;
            fc_s[jl][b0 + 1] = wf_s[jl] * hn1;
        }
        __syncthreads();
        if (tid < BB) {
            g_fpart[cta * BB + tid] =
                fc_s[0][tid] + fc_s[1][tid] + fc_s[2][tid] + fc_s[3][tid];
        }
        bar_arrive();   // barrier #1 arrive; wait is hidden behind A*c below

        // ================= phase 2: c_new = A_t c + f B_t =================
        float p0 = 0.f, p1 = 0.f;
        {
            const float* Arow = A_stack + ((size_t)t * NN + jg) * NN;
            #pragma unroll 4
            for (int k = 0; k < NN; k += 4) {
                float4 a4 = __ldg((const float4*)(Arow + k));
                float2 c2;
                c2 = __ldcg((const float2*)(c_cur + (k + 0) * BB + b0));
                p0 += a4.x * c2.x;  p1 += a4.x * c2.y;
                c2 = __ldcg((const float2*)(c_cur + (k + 1) * BB + b0));
                p0 += a4.y * c2.x;  p1 += a4.y * c2.y;
                c2 = __ldcg((const float2*)(c_cur + (k + 2) * BB + b0));
                p0 += a4.z * c2.x;  p1 += a4.z * c2.y;
                c2 = __ldcg((const float2*)(c_cur + (k + 3) * BB + b0));
                p0 += a4.w * c2.x;  p1 += a4.w * c2.y;
            }
        }
        bar_wait((unsigned)(2 * t + 1) * NCTA);   // all f partials published

        if (tid < BB) {
            float s = 0.f;
            #pragma unroll 8
            for (int q = 0; q < NCTA; ++q) s += __ldcg(g_fpart + q * BB + tid);
            f_s[tid] = bf0 + wf0 * x[tid * TT + t] + s;
        }
        __syncthreads();

        {
            float Bt = B_stack[t * NN + jg];
            float cn0 = p0 + f_s[b0]     * Bt;
            float cn1 = p1 + f_s[b0 + 1] * Bt;
            g_c[nxt][jg * BB + b0]     = cn0;
            g_c[nxt][jg * BB + b0 + 1] = cn1;
            if (t == TT - 1) {
                out_cf[(b0 + 0) * NN + jg] = cn0;
                out_cf[(b0 + 1) * NN + jg] = cn1;
            }
        }
        bar_arrive();
        bar_wait((unsigned)(2 * t + 2) * NCTA);   // barrier #2: step complete
    }
}

extern "C" void kernel_launch(void* const* d_in, const int* in_sizes, int n_in,
                              void* d_out, int out_size) {
    const float* x   = (const float*)d_in[0];
    const float* h0  = (const float*)d_in[1];
    const float* c0  = (const float*)d_in[2];
    const float* Wi  = (const float*)d_in[3];
    const float* bi  = (const float*)d_in[4];
    const float* Wh  = (const float*)d_in[5];
    const float* bh  = (const float*)d_in[6];
    const float* Wf  = (const float*)d_in[7];
    const float* bf  = (const float*)d_in[8];
    const float* A_s = (const float*)d_in[9];
    const float* B_s = (const float*)d_in[10];
    float* out = (float*)d_out;

    hippo_init<<<128, 256>>>(h0, c0);
    hippo_persistent<<<NCTA, NTHR>>>(x, Wi, bi, Wh, bh, Wf, bf, A_s, B_s, out);
}

// round 3
// speedup vs baseline: 2.1663x; 2.1663x over previous
#include <cuda_runtime.h>
#include <math.h>

#define BB    128   // batch
#define TT    512   // timesteps
#define NNH   512   // hidden
#define NCOLT 16    // column tiles
#define NBT   8     // batch tiles
#define NCTA  (NCOLT * NBT)   // 128 CTAs
#define NJ    32    // columns per CTA
#define MB    16    // batches per CTA
#define NTHR  256
#define WP    516   // weight row pitch (floats) — breaks bank conflicts, keeps 16B align

// -------- persistent device state --------
__device__ float g_c[2][NNH * BB];      // [n][b] transposed, double buffered
__device__ float g_h[2][NNH * BB];
__device__ float g_fpart[NCOLT * BB];   // f partials per column-tile
__device__ unsigned int g_bar;

__global__ void hippo_init(const float* __restrict__ h0, const float* __restrict__ c0) {
    int idx = blockIdx.x * blockDim.x + threadIdx.x;
    if (idx == 0) g_bar = 0u;
    int total = NNH * BB;
    for (int i = idx; i < total; i += gridDim.x * blockDim.x) {
        int n = i / BB;
        int b = i % BB;
        g_c[0][i] = c0[b * NNH + n];
        g_h[0][i] = h0[b * NNH + n];
    }
}

__device__ __forceinline__ void bar_arrive() {
    __syncthreads();
    if (threadIdx.x == 0) {
        __threadfence();
        atomicAdd(&g_bar, 1u);
    }
}
__device__ __forceinline__ void bar_wait(unsigned int target) {
    if (threadIdx.x == 0) {
        while (atomicAdd(&g_bar, 0u) < target) { __nanosleep(32); }
        __threadfence();
    }
    __syncthreads();
}

// dynamic smem layout (floats):
//   Wi_s[NJ][WP], Wh_s[NJ][WP], c_s[NNH][MB], h_s[NNH][MB],
//   fc_s[NJ][17], f_s[MB], wx_s[NJ], bb_s[NJ], wf_s[NJ]
#define SM_FLOATS (2 * NJ * WP + 2 * NNH * MB + NJ * 17 + MB + 3 * NJ)
#define SM_BYTES  (SM_FLOATS * 4)

__global__ __launch_bounds__(NTHR, 1) void hippo_persistent(
    const float* __restrict__ x,        // (B,T,1)
    const float* __restrict__ Wi,       // (N, N+1)
    const float* __restrict__ bi,
    const float* __restrict__ Wh,
    const float* __restrict__ bh,
    const float* __restrict__ Wf,       // (1, N+1)
    const float* __restrict__ bfv,
    const float* __restrict__ A_stack,  // (T,N,N)
    const float* __restrict__ B_stack,  // (T,N)
    float* __restrict__ out)            // hs (B,T,N) then c_f (B,N)
{
    extern __shared__ float sm[];
    float* Wi_s = sm;                        // NJ*WP
    float* Wh_s = Wi_s + NJ * WP;            // NJ*WP
    float* c_s  = Wh_s + NJ * WP;            // NNH*MB
    float* h_s  = c_s + NNH * MB;            // NNH*MB
    float* fc_s = h_s + NNH * MB;            // NJ*17
    float* f_s  = fc_s + NJ * 17;            // MB
    float* wx_s = f_s + MB;                  // NJ
    float* bb_s = wx_s + NJ;                 // NJ
    float* wf_s = bb_s + NJ;                 // NJ

    const int cta   = blockIdx.x;
    const int ct    = cta & (NCOLT - 1);     // column tile 0..15
    const int bt    = cta >> 4;              // batch tile  0..7
    const int jbase = ct * NJ;
    const int bbase = bt * MB;
    const int tid   = threadIdx.x;
    const int j     = tid >> 3;              // 0..31
    const int bp    = tid & 7;               // 0..7
    const int b0    = 2 * bp;                // local batches b0, b0+1
    const int jg    = jbase + j;
    const int bg0   = bbase + b0;

    // ---- one-time: load weight slices ----
    for (int i = tid; i < NJ * NNH; i += NTHR) {
        int r = i / NNH, k = i % NNH;
        Wi_s[r * WP + k] = Wi[(jbase + r) * (NNH + 1) + 1 + k];
        Wh_s[r * WP + k] = Wh[(jbase + r) * (NNH + 1) + 1 + k];
    }
    if (tid < NJ) {
        wx_s[tid] = Wi[(jbase + tid) * (NNH + 1)] + Wh[(jbase + tid) * (NNH + 1)];
        bb_s[tid] = bi[jbase + tid] + bh[jbase + tid];
        wf_s[tid] = Wf[1 + jbase + tid];
    }
    // ---- initial state staging ----
    for (int i = tid; i < (NNH * MB) / 4; i += NTHR) {
        int n = i >> 2, q = i & 3;
        *(float4*)(c_s + n * MB + 4 * q) =
            *(const float4*)(g_c[0] + n * BB + bbase + 4 * q);
        *(float4*)(h_s + n * MB + 4 * q) =
            *(const float4*)(g_h[0] + n * BB + bbase + 4 * q);
    }
    __syncthreads();

    const float wf0 = Wf[0];
    const float bf0 = bfv[0];
    float* out_hs = out;
    float* out_cf = out + (size_t)BB * TT * NNH;

    const float* wi = Wi_s + j * WP;
    const float* wh = Wh_s + j * WP;

    for (int t = 0; t < TT; ++t) {
        const int nxt = (t & 1) ^ 1;

        // ================= phase 1: gates from SMEM =================
        float a0 = 0.f, a1 = 0.f;
        #pragma unroll 4
        for (int k = 0; k < NNH; k += 4) {
            float4 wi4 = *(const float4*)(wi + k);
            float4 wh4 = *(const float4*)(wh + k);
            float2 c2, h2;
            c2 = *(const float2*)(c_s + (k + 0) * MB + b0);
            h2 = *(const float2*)(h_s + (k + 0) * MB + b0);
            a0 += wi4.x * c2.x + wh4.x * h2.x;  a1 += wi4.x * c2.y + wh4.x * h2.y;
            c2 = *(const float2*)(c_s + (k + 1) * MB + b0);
            h2 = *(const float2*)(h_s + (k + 1) * MB + b0);
            a0 += wi4.y * c2.x + wh4.y * h2.x;  a1 += wi4.y * c2.y + wh4.y * h2.y;
            c2 = *(const float2*)(c_s + (k + 2) * MB + b0);
            h2 = *(const float2*)(h_s + (k + 2) * MB + b0);
            a0 += wi4.z * c2.x + wh4.z * h2.x;  a1 += wi4.z * c2.y + wh4.z * h2.y;
            c2 = *(const float2*)(c_s + (k + 3) * MB + b0);
            h2 = *(const float2*)(h_s + (k + 3) * MB + b0);
            a0 += wi4.w * c2.x + wh4.w * h2.x;  a1 += wi4.w * c2.y + wh4.w * h2.y;
        }
        float hn0, hn1;
        {
            float xb0 = x[(bg0 + 0) * TT + t];
            float xb1 = x[(bg0 + 1) * TT + t];
            float g0 = a0 + bb_s[j] + wx_s[j] * xb0;
            float g1 = a1 + bb_s[j] + wx_s[j] * xb1;
            float o0 = 1.f / (1.f + expf(-g0));
            float o1 = 1.f / (1.f + expf(-g1));
            float cj0 = c_s[jg * MB + b0];
            float cj1 = c_s[jg * MB + b0 + 1];
            hn0 = o0 * tanhf(cj0);
            hn1 = o1 * tanhf(cj1);
            g_h[nxt][jg * BB + bg0]     = hn0;
            g_h[nxt][jg * BB + bg0 + 1] = hn1;
            out_hs[(size_t)(bg0 + 0) * TT * NNH + (size_t)t * NNH + jg] = hn0;
            out_hs[(size_t)(bg0 + 1) * TT * NNH + (size_t)t * NNH + jg] = hn1;
            fc_s[j * 17 + b0]     = wf_s[j] * hn0;
            fc_s[j * 17 + b0 + 1] = wf_s[j] * hn1;
        }
        __syncthreads();
        if (tid < MB) {
            float s = 0.f;
            #pragma unroll
            for (int jj = 0; jj < NJ; ++jj) s += fc_s[jj * 17 + tid];
            g_fpart[ct * BB + bbase + tid] = s;
        }
        bar_arrive();   // barrier #1 (h_new + f partials visible)

        // ============ phase 2: A_t·c from SMEM/L2 (hides barrier #1) ============
        float p0 = 0.f, p1 = 0.f;
        {
            const float* Arow = A_stack + ((size_t)t * NNH + jg) * NNH;
            #pragma unroll 8
            for (int k = 0; k < NNH; k += 4) {
                float4 a4 = __ldg((const float4*)(Arow + k));
                float2 c2;
                c2 = *(const float2*)(c_s + (k + 0) * MB + b0);
                p0 += a4.x * c2.x;  p1 += a4.x * c2.y;
                c2 = *(const float2*)(c_s + (k + 1) * MB + b0);
                p0 += a4.y * c2.x;  p1 += a4.y * c2.y;
                c2 = *(const float2*)(c_s + (k + 2) * MB + b0);
                p0 += a4.z * c2.x;  p1 += a4.z * c2.y;
                c2 = *(const float2*)(c_s + (k + 3) * MB + b0);
                p0 += a4.w * c2.x;  p1 += a4.w * c2.y;
            }
        }
        bar_wait((unsigned)(2 * t + 1) * NCTA);

        if (tid < MB) {
            float s = 0.f;
            #pragma unroll
            for (int q = 0; q < NCOLT; ++q) s += __ldcg(g_fpart + q * BB + bbase + tid);
            f_s[tid] = bf0 + wf0 * x[(bbase + tid) * TT + t] + s;
        }
        __syncthreads();

        {
            float Bt = B_stack[t * NNH + jg];
            float cn0 = p0 + f_s[b0]     * Bt;
            float cn1 = p1 + f_s[b0 + 1] * Bt;
            g_c[nxt][jg * BB + bg0]     = cn0;
            g_c[nxt][jg * BB + bg0 + 1] = cn1;
            if (t == TT - 1) {
                out_cf[(bg0 + 0) * NNH + jg] = cn0;
                out_cf[(bg0 + 1) * NNH + jg] = cn1;
            }
        }

        // stage h for next step (valid since barrier #1 passed)
        for (int i = tid; i < (NNH * MB) / 4; i += NTHR) {
            int n = i >> 2, q = i & 3;
            *(float4*)(h_s + n * MB + 4 * q) =
                __ldcg((const float4*)(g_h[nxt] + n * BB + bbase + 4 * q));
        }
        bar_arrive();                                 // barrier #2
        bar_wait((unsigned)(2 * t + 2) * NCTA);       // all c_new visible
        for (int i = tid; i < (NNH * MB) / 4; i += NTHR) {
            int n = i >> 2, q = i & 3;
            *(float4*)(c_s + n * MB + 4 * q) =
                __ldcg((const float4*)(g_c[nxt] + n * BB + bbase + 4 * q));
        }
        __syncthreads();
    }
}

extern "C" void kernel_launch(void* const* d_in, const int* in_sizes, int n_in,
                              void* d_out, int out_size) {
    const float* x   = (const float*)d_in[0];
    const float* h0  = (const float*)d_in[1];
    const float* c0  = (const float*)d_in[2];
    const float* Wi  = (const float*)d_in[3];
    const float* bi  = (const float*)d_in[4];
    const float* Wh  = (const float*)d_in[5];
    const float* bh  = (const float*)d_in[6];
    const float* Wf  = (const float*)d_in[7];
    const float* bf  = (const float*)d_in[8];
    const float* A_s = (const float*)d_in[9];
    const float* B_s = (const float*)d_in[10];
    float* out = (float*)d_out;

    cudaFuncSetAttribute(hippo_persistent,
                         cudaFuncAttributeMaxDynamicSharedMemorySize, SM_BYTES);
    hippo_init<<<128, 256>>>(h0, c0);
    hippo_persistent<<<NCTA, NTHR, SM_BYTES>>>(x, Wi, bi, Wh, bh, Wf, bf,
                                               A_s, B_s, out);
}

// round 4
// speedup vs baseline: 3.1785x; 1.4673x over previous
#include <cuda_runtime.h>
#include <math.h>
#include <stdint.h>

#define BB    128   // batch
#define TT    512   // timesteps
#define NNH   512   // hidden
#define NCOLT 16    // column tiles
#define NBT   8     // batch tiles
#define NCTA  128
#define NJ    32    // columns per CTA
#define MB    16    // batches per CTA
#define NTHR  256
#define WP    520   // weight pitch (floats): 2j+kh bank-quad spread, 16B aligned
#define SP    20    // state pitch (floats), [k][b]: 4kh+5kk+bq quad spread

// -------- persistent device state --------
__device__ float g_c[2][NNH * BB];      // [n][b], double buffered
__device__ float g_h[2][NNH * BB];
__device__ float g_fpart[NCOLT * BB];
__device__ unsigned int g_bar;

__global__ void hippo_init(const float* __restrict__ h0, const float* __restrict__ c0) {
    int idx = blockIdx.x * blockDim.x + threadIdx.x;
    if (idx == 0) g_bar = 0u;
    int total = NNH * BB;
    for (int i = idx; i < total; i += gridDim.x * blockDim.x) {
        int n = i / BB;
        int b = i % BB;
        g_c[0][i] = c0[b * NNH + n];
        g_h[0][i] = h0[b * NNH + n];
    }
}

__device__ __forceinline__ void bar_arrive() {
    __syncthreads();
    if (threadIdx.x == 0) {
        __threadfence();
        atomicAdd(&g_bar, 1u);
    }
}
__device__ __forceinline__ void bar_wait(unsigned int target) {
    if (threadIdx.x == 0) {
        while (*(volatile unsigned int*)&g_bar < target) { }
        __threadfence();
    }
    __syncthreads();
}

// packed fp32 helpers
__device__ __forceinline__ void fma2(uint64_t& d, uint64_t a, uint64_t b) {
    asm("fma.rn.f32x2 %0, %1, %2, %0;" : "+l"(d) : "l"(a), "l"(b));
}
__device__ __forceinline__ uint64_t splat2(float w) {
    uint64_t r;
    asm("mov.b64 %0, {%1, %1};" : "=l"(r) : "f"(w));
    return r;
}
__device__ __forceinline__ float2 unpack2(uint64_t v) {
    float2 r;
    asm("mov.b64 {%0, %1}, %2;" : "=f"(r.x), "=f"(r.y) : "l"(v));
    return r;
}

// smem: Wi[NJ*WP] Wh[NJ*WP] c[NNH*SP] h[NNH*SP] fc[NJ*18] f[MB] wx[NJ] bb[NJ] wf[NJ]
#define SM_FLOATS (2 * NJ * WP + 2 * NNH * SP + NJ * 18 + MB + 3 * NJ)
#define SM_BYTES  (SM_FLOATS * 4)

__global__ __launch_bounds__(NTHR, 1) void hippo_persistent(
    const float* __restrict__ x,
    const float* __restrict__ Wi,
    const float* __restrict__ bi,
    const float* __restrict__ Wh,
    const float* __restrict__ bh,
    const float* __restrict__ Wf,
    const float* __restrict__ bfv,
    const float* __restrict__ A_stack,
    const float* __restrict__ B_stack,
    float* __restrict__ out)
{
    extern __shared__ float sm[];
    float* Wi_s = sm;
    float* Wh_s = Wi_s + NJ * WP;
    float* c_s  = Wh_s + NJ * WP;
    float* h_s  = c_s + NNH * SP;
    float* fc_s = h_s + NNH * SP;
    float* f_s  = fc_s + NJ * 18;
    float* wx_s = f_s + MB;
    float* bb_s = wx_s + NJ;
    float* wf_s = bb_s + NJ;

    const int cta   = blockIdx.x;
    const int ct    = cta & (NCOLT - 1);
    const int bt    = cta >> 4;
    const int jbase = ct * NJ;
    const int bbase = bt * MB;
    const int tid   = threadIdx.x;
    const int j     = tid >> 3;          // 0..31 column
    const int kh    = (tid >> 2) & 1;    // K-half (interleaved 4-blocks)
    const int bq    = tid & 3;           // batch quad 0..3
    const int jg    = jbase + j;
    const int lb    = bq * 4 + kh * 2;   // this lane's 2 local batches
    const int bg    = bbase + lb;

    // ---- one-time weight load ----
    for (int i = tid; i < NJ * NNH; i += NTHR) {
        int r = i / NNH, k = i % NNH;
        Wi_s[r * WP + k] = Wi[(jbase + r) * (NNH + 1) + 1 + k];
        Wh_s[r * WP + k] = Wh[(jbase + r) * (NNH + 1) + 1 + k];
    }
    if (tid < NJ) {
        wx_s[tid] = Wi[(jbase + tid) * (NNH + 1)] + Wh[(jbase + tid) * (NNH + 1)];
        bb_s[tid] = bi[jbase + tid] + bh[jbase + tid];
        wf_s[tid] = Wf[1 + jbase + tid];
    }
    // ---- initial state staging into [k][b] pitch-SP ----
    for (int i = tid; i < NNH * 4; i += NTHR) {
        int n = i >> 2, q = i & 3;
        *(float4*)(c_s + n * SP + 4 * q) =
            *(const float4*)(g_c[0] + n * BB + bbase + 4 * q);
        *(float4*)(h_s + n * SP + 4 * q) =
            *(const float4*)(g_h[0] + n * BB + bbase + 4 * q);
    }
    __syncthreads();

    const float wf0 = Wf[0];
    const float bf0 = bfv[0];
    float* out_hs = out;
    float* out_cf = out + (size_t)BB * TT * NNH;

    const float* wi = Wi_s + j * WP;
    const float* wh = Wh_s + j * WP;

    for (int t = 0; t < TT; ++t) {
        const int nxt = (t & 1) ^ 1;

        float xb0 = __ldcg(&x[(size_t)(bg + 0) * TT + t]);
        float xb1 = __ldcg(&x[(size_t)(bg + 1) * TT + t]);

        // ===== fused loop: gates (Wi·c + Wh·h) and p = A_t·c =====
        uint64_t aI0 = 0, aI1 = 0, aH0 = 0, aH1 = 0, aP0 = 0, aP1 = 0;
        {
            const float* Arow = A_stack + ((size_t)t * NNH + jg) * NNH;
            const int k0base = kh * 4;
            #pragma unroll 4
            for (int m = 0; m < 64; ++m) {
                const int k = k0base + m * 8;
                float4 a4  = __ldg((const float4*)(Arow + k));
                float4 wi4 = *(const float4*)(wi + k);
                float4 wh4 = *(const float4*)(wh + k);
                {
                    ulonglong2 cc = *(const ulonglong2*)(c_s + (k + 0) * SP + bq * 4);
                    ulonglong2 hh = *(const ulonglong2*)(h_s + (k + 0) * SP + bq * 4);
                    uint64_t ws = splat2(wi4.x), vs = splat2(wh4.x), as = splat2(a4.x);
                    fma2(aI0, ws, cc.x); fma2(aI1, ws, cc.y);
                    fma2(aH0, vs, hh.x); fma2(aH1, vs, hh.y);
                    fma2(aP0, as, cc.x); fma2(aP1, as, cc.y);
                }
                {
                    ulonglong2 cc = *(const ulonglong2*)(c_s + (k + 1) * SP + bq * 4);
                    ulonglong2 hh = *(const ulonglong2*)(h_s + (k + 1) * SP + bq * 4);
                    uint64_t ws = splat2(wi4.y), vs = splat2(wh4.y), as = splat2(a4.y);
                    fma2(aI0, ws, cc.x); fma2(aI1, ws, cc.y);
                    fma2(aH0, vs, hh.x); fma2(aH1, vs, hh.y);
                    fma2(aP0, as, cc.x); fma2(aP1, as, cc.y);
                }
                {
                    ulonglong2 cc = *(const ulonglong2*)(c_s + (k + 2) * SP + bq * 4);
                    ulonglong2 hh = *(const ulonglong2*)(h_s + (k + 2) * SP + bq * 4);
                    uint64_t ws = splat2(wi4.z), vs = splat2(wh4.z), as = splat2(a4.z);
                    fma2(aI0, ws, cc.x); fma2(aI1, ws, cc.y);
                    fma2(aH0, vs, hh.x); fma2(aH1, vs, hh.y);
                    fma2(aP0, as, cc.x); fma2(aP1, as, cc.y);
                }
                {
                    ulonglong2 cc = *(const ulonglong2*)(c_s + (k + 3) * SP + bq * 4);
                    ulonglong2 hh = *(const ulonglong2*)(h_s + (k + 3) * SP + bq * 4);
                    uint64_t ws = splat2(wi4.w), vs = splat2(wh4.w), as = splat2(a4.w);
                    fma2(aI0, ws, cc.x); fma2(aI1, ws, cc.y);
                    fma2(aH0, vs, hh.x); fma2(aH1, vs, hh.y);
                    fma2(aP0, as, cc.x); fma2(aP1, as, cc.y);
                }
            }
        }

        // combine gate partials, reduce across kh partner (lane^4)
        float2 i0 = unpack2(aI0), i1 = unpack2(aI1);
        float2 h0v = unpack2(aH0), h1v = unpack2(aH1);
        float g0 = i0.x + h0v.x, g1 = i0.y + h0v.y;
        float g2 = i1.x + h1v.x, g3 = i1.y + h1v.y;
        g0 += __shfl_xor_sync(0xffffffffu, g0, 4);
        g1 += __shfl_xor_sync(0xffffffffu, g1, 4);
        g2 += __shfl_xor_sync(0xffffffffu, g2, 4);
        g3 += __shfl_xor_sync(0xffffffffu, g3, 4);

        float ga = kh ? g2 : g0;
        float gb = kh ? g3 : g1;

        float hna, hnb;
        {
            float bbv = bb_s[j], wxv = wx_s[j], wfv = wf_s[j];
            float ea = ga + bbv + wxv * xb0;
            float eb = gb + bbv + wxv * xb1;
            float oa = 1.f / (1.f + __expf(-ea));
            float ob = 1.f / (1.f + __expf(-eb));
            float ca = c_s[jg * SP + lb];
            float cb = c_s[jg * SP + lb + 1];
            hna = oa * tanhf(ca);
            hnb = ob * tanhf(cb);
            *(float2*)(&g_h[nxt][jg * BB + bg]) = make_float2(hna, hnb);
            *(float2*)(&fc_s[j * 18 + lb]) = make_float2(wfv * hna, wfv * hnb);
        }
        __syncthreads();
        if (tid < MB) {
            float s = 0.f;
            #pragma unroll
            for (int jj = 0; jj < NJ; ++jj) s += fc_s[jj * 18 + tid];
            g_fpart[ct * BB + bbase + tid] = s;
        }
        bar_arrive();   // #1: h_new + f partials visible

        // hide behind barrier: hs output stores + p reduction
        {
            size_t ob = (size_t)bg * TT * NNH + (size_t)t * NNH + jg;
            out_hs[ob] = hna;
            out_hs[ob + (size_t)TT * NNH] = hnb;
        }
        float2 p0v = unpack2(aP0), p1v = unpack2(aP1);
        float p0 = p0v.x, p1 = p0v.y, p2 = p1v.x, p3 = p1v.y;
        p0 += __shfl_xor_sync(0xffffffffu, p0, 4);
        p1 += __shfl_xor_sync(0xffffffffu, p1, 4);
        p2 += __shfl_xor_sync(0xffffffffu, p2, 4);
        p3 += __shfl_xor_sync(0xffffffffu, p3, 4);
        float pa = kh ? p2 : p0;
        float pb = kh ? p3 : p1;

        bar_wait((unsigned)(2 * t + 1) * NCTA);

        // stage h for next step (all 512 columns)
        for (int i = tid; i < NNH * 4; i += NTHR) {
            int n = i >> 2, q = i & 3;
            *(float4*)(h_s + n * SP + 4 * q) =
                __ldcg((const float4*)(g_h[nxt] + n * BB + bbase + 4 * q));
        }
        if (tid < MB) {
            float s = 0.f;
            #pragma unroll
            for (int q = 0; q < NCOLT; ++q)
                s += __ldcg(&g_fpart[q * BB + bbase + tid]);
            f_s[tid] = bf0 + wf0 * __ldcg(&x[(size_t)(bbase + tid) * TT + t]) + s;
        }
        __syncthreads();

        {
            float Bt = __ldg(&B_stack[t * NNH + jg]);
            float cna = pa + f_s[lb] * Bt;
            float cnb = pb + f_s[lb + 1] * Bt;
            *(float2*)(&g_c[nxt][jg * BB + bg]) = make_float2(cna, cnb);
            if (t == TT - 1) {
                out_cf[(size_t)(bg + 0) * NNH + jg] = cna;
                out_cf[(size_t)(bg + 1) * NNH + jg] = cnb;
            }
        }
        bar_arrive();                               // #2
        bar_wait((unsigned)(2 * t + 2) * NCTA);     // all c_new visible
        for (int i = tid; i < NNH * 4; i += NTHR) {
            int n = i >> 2, q = i & 3;
            *(float4*)(c_s + n * SP + 4 * q) =
                __ldcg((const float4*)(g_c[nxt] + n * BB + bbase + 4 * q));
        }
        __syncthreads();
    }
}

extern "C" void kernel_launch(void* const* d_in, const int* in_sizes, int n_in,
                              void* d_out, int out_size) {
    const float* x   = (const float*)d_in[0];
    const float* h0  = (const float*)d_in[1];
    const float* c0  = (const float*)d_in[2];
    const float* Wi  = (const float*)d_in[3];
    const float* bi  = (const float*)d_in[4];
    const float* Wh  = (const float*)d_in[5];
    const float* bh  = (const float*)d_in[6];
    const float* Wf  = (const float*)d_in[7];
    const float* bf  = (const float*)d_in[8];
    const float* A_s = (const float*)d_in[9];
    const float* B_s = (const float*)d_in[10];
    float* out = (float*)d_out;

    cudaFuncSetAttribute(hippo_persistent,
                         cudaFuncAttributeMaxDynamicSharedMemorySize, SM_BYTES);
    hippo_init<<<128, 256>>>(h0, c0);
    hippo_persistent<<<NCTA, NTHR, SM_BYTES>>>(x, Wi, bi, Wh, bh, Wf, bf,
                                               A_s, B_s, out);
}